// round 14
// baseline (speedup 1.0000x reference)
#include <cuda_runtime.h>

// Problem constants
#define B_ROWS 64
#define N_COLS 262144
#define N4 (N_COLS / 4)                 // 65536 float4 per row
#define THREADS 256
#define V4_PER_THREAD 4                 // 16 elements per thread per iter
#define F4_PER_ITER (THREADS * V4_PER_THREAD)           // 1024 float4
#define ITERS 4
#define F4_PER_BLOCK (F4_PER_ITER * ITERS)              // 4096 float4
#define BLOCKS_PER_ROW (N4 / F4_PER_BLOCK)              // 16
#define TOTAL_BLOCKS (B_ROWS * BLOCKS_PER_ROW)          // 1024 -> SINGLE WAVE,
                                                        // 8 blocks/SM, 55 w/SM

// Per-block partial: (sum_t, sum t*log2(p), sum (1-t)*log2(1-p), pad).
// Every slot overwritten unconditionally each launch -> no zeroing needed.
__device__ float4 g_part[TOTAL_BLOCKS];
__device__ unsigned int g_count;        // zero-init at load; reset by last block

// Release-only arrival: orders the prior partial STG; no acquire -> no L1
// flush on the issuing SM. Only the single last block pays one acquire fence.
__device__ __forceinline__ unsigned int arrive_release(unsigned int* ctr) {
    unsigned int prev;
    asm volatile("atom.add.release.gpu.u32 %0, [%1], 1;"
                 : "=r"(prev) : "l"(ctr) : "memory");
    return prev;
}

__global__ __launch_bounds__(THREADS) void bce_fused_kernel(
    const float4* __restrict__ p4, const float4* __restrict__ t4,
    float* __restrict__ out) {
    const int row = blockIdx.y;
    const int chunk = blockIdx.x;
    const int tid = threadIdx.x;
    const int base0 = row * N4 + chunk * F4_PER_BLOCK + tid;   // fits in int

    float st = 0.f, s1 = 0.f, sq = 0.f, sw = 0.f;

#pragma unroll
    for (int it = 0; it < ITERS; it++) {
        const int base = base0 + it * F4_PER_ITER;

        // Front-batched 8x LDG.128 burst per iteration (proven MLP pattern)
        float4 pv[V4_PER_THREAD], tv[V4_PER_THREAD];
#pragma unroll
        for (int v = 0; v < V4_PER_THREAD; v++) {
            pv[v] = __ldcg(&p4[base + v * THREADS]);
            tv[v] = __ldcg(&t4[base + v * THREADS]);
        }

#pragma unroll
        for (int v = 0; v < V4_PER_THREAD; v++) {
            const float pe[4] = {pv[v].x, pv[v].y, pv[v].z, pv[v].w};
            const float te[4] = {tv[v].x, tv[v].y, tv[v].z, tv[v].w};
#pragma unroll
            for (int e = 0; e < 4; e++) {
                float lp = __log2f(pe[e]);        // scaled by ln2 in finalize
                float lq = __log2f(1.0f - pe[e]);
                st += te[e];
                s1 = fmaf(te[e], lp, s1);
                sq += lq;
                sw = fmaf(te[e], lq, sw);
            }
        }
    }
    float s2 = sq - sw;

    // warp reduce
#pragma unroll
    for (int o = 16; o > 0; o >>= 1) {
        st += __shfl_down_sync(0xFFFFFFFFu, st, o);
        s1 += __shfl_down_sync(0xFFFFFFFFu, s1, o);
        s2 += __shfl_down_sync(0xFFFFFFFFu, s2, o);
    }

    __shared__ float sh_st[THREADS / 32], sh_s1[THREADS / 32], sh_s2[THREADS / 32];
    __shared__ int is_last;
    const int warp = tid >> 5;
    const int lane = tid & 31;
    if (lane == 0) { sh_st[warp] = st; sh_s1[warp] = s1; sh_s2[warp] = s2; }
    __syncthreads();

    if (warp == 0) {
        const int nw = THREADS / 32;   // 8
        float a = (lane < nw) ? sh_st[lane] : 0.f;
        float b = (lane < nw) ? sh_s1[lane] : 0.f;
        float c = (lane < nw) ? sh_s2[lane] : 0.f;
#pragma unroll
        for (int o = 4; o > 0; o >>= 1) {
            a += __shfl_down_sync(0xFFFFFFFFu, a, o);
            b += __shfl_down_sync(0xFFFFFFFFu, b, o);
            c += __shfl_down_sync(0xFFFFFFFFu, c, o);
        }
        if (lane == 0) {
            g_part[row * BLOCKS_PER_ROW + chunk] = make_float4(a, b, c, 0.f);
            is_last = (arrive_release(&g_count) == TOTAL_BLOCKS - 1u) ? 1 : 0;
        }
    }
    __syncthreads();                   // ALL warps stay (R12 lesson), then exit
    if (!is_last) return;

    // ---- finalize in the single last block (1024 partials, L2-hot) ----
    asm volatile("fence.acq_rel.gpu;" ::: "memory");   // one IVALL, once

    // 4 threads per row x 64 rows = 256 threads; 4 partials per thread.
    {
        const int r = tid >> 2;        // 0..63
        const int sub = tid & 3;       // 0..3

        float a = 0.f, b = 0.f, c = 0.f;
#pragma unroll
        for (int k = 0; k < BLOCKS_PER_ROW / 4; k++) {   // 4 iters
            float4 v = g_part[r * BLOCKS_PER_ROW + sub + k * 4];
            a += v.x; b += v.y; c += v.z;
        }
#pragma unroll
        for (int o = 2; o > 0; o >>= 1) {
            a += __shfl_down_sync(0xFFFFFFFFu, a, o, 4);
            b += __shfl_down_sync(0xFFFFFFFFu, b, o, 4);
            c += __shfl_down_sync(0xFFFFFFFFu, c, o, 4);
        }

        __shared__ double sh_row[B_ROWS];
        if (sub == 0) {
            const double LN2 = 0.6931471805599453;
            double beta = 1.0 - (double)a / (double)N_COLS;
            sh_row[r] = (beta * (double)b + (1.0 - beta) * (double)c) * LN2;
        }
        __syncthreads();

        if (tid < 64) {
            double s = sh_row[tid];
#pragma unroll
            for (int o = 16; o > 0; o >>= 1)
                s += __shfl_down_sync(0xFFFFFFFFu, s, o);
            __shared__ double sh2[2];
            if ((tid & 31) == 0) sh2[tid >> 5] = s;
            __syncthreads();
            if (tid == 0) {
                out[0] = (float)(-(sh2[0] + sh2[1]));
                *((volatile unsigned int*)&g_count) = 0u;  // reset for replay
            }
        }
    }
}

extern "C" void kernel_launch(void* const* d_in, const int* in_sizes, int n_in,
                              void* d_out, int out_size) {
    const float4* p = (const float4*)d_in[0];  // input (probabilities)
    const float4* t = (const float4*)d_in[1];  // target
    float* out = (float*)d_out;

    dim3 grid(BLOCKS_PER_ROW, B_ROWS);
    bce_fused_kernel<<<grid, THREADS>>>(p, t, out);
}

// round 15
// speedup vs baseline: 1.0714x; 1.0714x over previous
#include <cuda_runtime.h>
#include <cuda_device_runtime_api.h>

// Problem constants
#define B_ROWS 64
#define N_COLS 262144
#define N4 (N_COLS / 4)                 // 65536 float4 per row
#define THREADS 256
#define V4_PER_THREAD 2                 // 8 elements/thread/array (MLP_p1=4/array)
#define F4_PER_BLOCK (THREADS * V4_PER_THREAD)          // 512 float4
#define BLOCKS_PER_ROW (N4 / F4_PER_BLOCK)              // 128
#define TOTAL_BLOCKS (B_ROWS * BLOCKS_PER_ROW)          // 8192

// Per-block partial: (sum_t, sum t*log2(p), sum (1-t)*log2(1-p), pad).
// Every slot overwritten unconditionally each launch -> no zeroing needed.
__device__ float4 g_part[TOTAL_BLOCKS];

__global__ __launch_bounds__(THREADS) void bce_main_kernel(
    const float4* __restrict__ p4, const float4* __restrict__ t4) {
    const int row = blockIdx.y;
    const int chunk = blockIdx.x;
    const int tid = threadIdx.x;
    const int base = row * N4 + chunk * F4_PER_BLOCK + tid;   // fits in int

    // Front-batch loads: 4 LDG.128 per thread (half of R9's burst -> less
    // cross-CTA L1tex queue contention per the spr_max model)
    float4 pv[V4_PER_THREAD], tv[V4_PER_THREAD];
#pragma unroll
    for (int v = 0; v < V4_PER_THREAD; v++) {
        pv[v] = __ldcg(&p4[base + v * THREADS]);
        tv[v] = __ldcg(&t4[base + v * THREADS]);
    }

    // Independent accumulator chains
    float st = 0.f, s1 = 0.f, sq = 0.f, sw = 0.f;
#pragma unroll
    for (int v = 0; v < V4_PER_THREAD; v++) {
        const float pe[4] = {pv[v].x, pv[v].y, pv[v].z, pv[v].w};
        const float te[4] = {tv[v].x, tv[v].y, tv[v].z, tv[v].w};
#pragma unroll
        for (int e = 0; e < 4; e++) {
            float lp = __log2f(pe[e]);            // scaled by ln2 in finalize
            float lq = __log2f(1.0f - pe[e]);
            st += te[e];
            s1 = fmaf(te[e], lp, s1);
            sq += lq;
            sw = fmaf(te[e], lq, sw);
        }
    }
    float s2 = sq - sw;                           // (1-t)*log2(1-p) summed

    // warp reduce
#pragma unroll
    for (int o = 16; o > 0; o >>= 1) {
        st += __shfl_down_sync(0xFFFFFFFFu, st, o);
        s1 += __shfl_down_sync(0xFFFFFFFFu, s1, o);
        s2 += __shfl_down_sync(0xFFFFFFFFu, s2, o);
    }

    __shared__ float sh_st[THREADS / 32], sh_s1[THREADS / 32], sh_s2[THREADS / 32];
    const int warp = tid >> 5;
    const int lane = tid & 31;
    if (lane == 0) { sh_st[warp] = st; sh_s1[warp] = s1; sh_s2[warp] = s2; }
    __syncthreads();

    if (warp == 0) {
        const int nw = THREADS / 32;   // 8
        float a = (lane < nw) ? sh_st[lane] : 0.f;
        float b = (lane < nw) ? sh_s1[lane] : 0.f;
        float c = (lane < nw) ? sh_s2[lane] : 0.f;
#pragma unroll
        for (int o = 4; o > 0; o >>= 1) {
            a += __shfl_down_sync(0xFFFFFFFFu, a, o);
            b += __shfl_down_sync(0xFFFFFFFFu, b, o);
            c += __shfl_down_sync(0xFFFFFFFFu, c, o);
        }
        if (lane == 0)
            g_part[row * BLOCKS_PER_ROW + chunk] = make_float4(a, b, c, 0.f);
    }
}

// PDL secondary (R11 mechanism, best measured): launch overlaps the primary;
// grid-dependency sync gives full memory visibility of all partials.
__global__ __launch_bounds__(512) void finalize_kernel(float* __restrict__ out) {
    cudaGridDependencySynchronize();

    const int tid = threadIdx.x;
    const int r = tid >> 3;            // 0..63
    const int sub = tid & 7;           // 0..7

    float a = 0.f, b = 0.f, c = 0.f;
#pragma unroll
    for (int k = 0; k < BLOCKS_PER_ROW / 8; k++) {   // 16 iters
        float4 v = g_part[r * BLOCKS_PER_ROW + sub + k * 8];
        a += v.x; b += v.y; c += v.z;
    }
#pragma unroll
    for (int o = 4; o > 0; o >>= 1) {
        a += __shfl_down_sync(0xFFFFFFFFu, a, o, 8);
        b += __shfl_down_sync(0xFFFFFFFFu, b, o, 8);
        c += __shfl_down_sync(0xFFFFFFFFu, c, o, 8);
    }

    __shared__ double sh_row[B_ROWS];
    if (sub == 0) {
        const double LN2 = 0.6931471805599453;
        double beta = 1.0 - (double)a / (double)N_COLS;
        sh_row[r] = (beta * (double)b + (1.0 - beta) * (double)c) * LN2;
    }
    __syncthreads();

    if (tid < 64) {
        double s = sh_row[tid];
#pragma unroll
        for (int o = 16; o > 0; o >>= 1)
            s += __shfl_down_sync(0xFFFFFFFFu, s, o);
        __shared__ double sh2[2];
        if ((tid & 31) == 0) sh2[tid >> 5] = s;
        __syncthreads();
        if (tid == 0) out[0] = (float)(-(sh2[0] + sh2[1]));
    }
}

extern "C" void kernel_launch(void* const* d_in, const int* in_sizes, int n_in,
                              void* d_out, int out_size) {
    const float4* p = (const float4*)d_in[0];  // input (probabilities)
    const float4* t = (const float4*)d_in[1];  // target
    float* out = (float*)d_out;

    dim3 grid(BLOCKS_PER_ROW, B_ROWS);
    bce_main_kernel<<<grid, THREADS>>>(p, t);

    // Programmatic dependent launch of the finalize kernel.
    cudaLaunchConfig_t cfg = {};
    cfg.gridDim = dim3(1, 1, 1);
    cfg.blockDim = dim3(512, 1, 1);
    cfg.dynamicSmemBytes = 0;
    cfg.stream = 0;
    cudaLaunchAttribute attrs[1];
    attrs[0].id = cudaLaunchAttributeProgrammaticStreamSerialization;
    attrs[0].val.programmaticStreamSerializationAllowed = 1;
    cfg.attrs = attrs;
    cfg.numAttrs = 1;
    cudaLaunchKernelEx(&cfg, finalize_kernel, out);
}

// round 16
// speedup vs baseline: 1.1525x; 1.0756x over previous
#include <cuda_runtime.h>
#include <cuda_device_runtime_api.h>

// Problem constants
#define B_ROWS 64
#define N_COLS 262144
#define THREADS 256
#define V8_PER_THREAD 2                 // 2 x 256-bit loads = 16 elems per array
#define ELEMS_PER_BLOCK (THREADS * V8_PER_THREAD * 8)   // 4096 elems
#define BLOCKS_PER_ROW (N_COLS / ELEMS_PER_BLOCK)       // 64
#define TOTAL_BLOCKS (B_ROWS * BLOCKS_PER_ROW)          // 4096 (same as R11)

// Per-block partial: (sum_t, sum t*log2(p), sum (1-t)*log2(1-p), pad).
// Every slot overwritten unconditionally each launch -> no zeroing needed.
__device__ float4 g_part[TOTAL_BLOCKS];

// Blackwell 256-bit global load (LDG.E.256): 8 floats in one instruction.
__device__ __forceinline__ void ldg256(const float* addr, float* r) {
    asm volatile("ld.global.v8.f32 {%0,%1,%2,%3,%4,%5,%6,%7}, [%8];"
                 : "=f"(r[0]), "=f"(r[1]), "=f"(r[2]), "=f"(r[3]),
                   "=f"(r[4]), "=f"(r[5]), "=f"(r[6]), "=f"(r[7])
                 : "l"(addr));
}

__global__ __launch_bounds__(THREADS) void bce_main_kernel(
    const float* __restrict__ p, const float* __restrict__ t) {
    const int row = blockIdx.y;
    const int chunk = blockIdx.x;
    const int tid = threadIdx.x;
    // thread reads 32B chunks; consecutive threads -> consecutive 32B: coalesced
    const int base = row * N_COLS + chunk * ELEMS_PER_BLOCK + tid * 8;

    // Front-batch: 4 x LDG.256 per thread (same bytes as R11's 8 x LDG.128,
    // half the load instructions / L1tex queue entries)
    float pv[V8_PER_THREAD][8], tv[V8_PER_THREAD][8];
#pragma unroll
    for (int v = 0; v < V8_PER_THREAD; v++) {
        ldg256(&p[base + v * THREADS * 8], pv[v]);
        ldg256(&t[base + v * THREADS * 8], tv[v]);
    }

    // Independent accumulator chains
    float st = 0.f, s1 = 0.f, sq = 0.f, sw = 0.f;
#pragma unroll
    for (int v = 0; v < V8_PER_THREAD; v++) {
#pragma unroll
        for (int e = 0; e < 8; e++) {
            float pe = pv[v][e];
            float te = tv[v][e];
            float lp = __log2f(pe);               // scaled by ln2 in finalize
            float lq = __log2f(1.0f - pe);
            st += te;
            s1 = fmaf(te, lp, s1);
            sq += lq;
            sw = fmaf(te, lq, sw);
        }
    }
    float s2 = sq - sw;                           // (1-t)*log2(1-p) summed

    // warp reduce
#pragma unroll
    for (int o = 16; o > 0; o >>= 1) {
        st += __shfl_down_sync(0xFFFFFFFFu, st, o);
        s1 += __shfl_down_sync(0xFFFFFFFFu, s1, o);
        s2 += __shfl_down_sync(0xFFFFFFFFu, s2, o);
    }

    __shared__ float sh_st[THREADS / 32], sh_s1[THREADS / 32], sh_s2[THREADS / 32];
    const int warp = tid >> 5;
    const int lane = tid & 31;
    if (lane == 0) { sh_st[warp] = st; sh_s1[warp] = s1; sh_s2[warp] = s2; }
    __syncthreads();

    if (warp == 0) {
        const int nw = THREADS / 32;   // 8
        float a = (lane < nw) ? sh_st[lane] : 0.f;
        float b = (lane < nw) ? sh_s1[lane] : 0.f;
        float c = (lane < nw) ? sh_s2[lane] : 0.f;
#pragma unroll
        for (int o = 4; o > 0; o >>= 1) {
            a += __shfl_down_sync(0xFFFFFFFFu, a, o);
            b += __shfl_down_sync(0xFFFFFFFFu, b, o);
            c += __shfl_down_sync(0xFFFFFFFFu, c, o);
        }
        if (lane == 0)
            g_part[row * BLOCKS_PER_ROW + chunk] = make_float4(a, b, c, 0.f);
    }
}

// PDL secondary (R11 mechanism): launch overlaps the primary; grid-dependency
// sync gives full memory visibility of all partials.
__global__ __launch_bounds__(512) void finalize_kernel(float* __restrict__ out) {
    cudaGridDependencySynchronize();

    const int tid = threadIdx.x;
    const int r = tid >> 3;            // 0..63
    const int sub = tid & 7;           // 0..7

    float a = 0.f, b = 0.f, c = 0.f;
#pragma unroll
    for (int k = 0; k < BLOCKS_PER_ROW / 8; k++) {   // 8 iters
        float4 v = g_part[r * BLOCKS_PER_ROW + sub + k * 8];
        a += v.x; b += v.y; c += v.z;
    }
#pragma unroll
    for (int o = 4; o > 0; o >>= 1) {
        a += __shfl_down_sync(0xFFFFFFFFu, a, o, 8);
        b += __shfl_down_sync(0xFFFFFFFFu, b, o, 8);
        c += __shfl_down_sync(0xFFFFFFFFu, c, o, 8);
    }

    __shared__ double sh_row[B_ROWS];
    if (sub == 0) {
        const double LN2 = 0.6931471805599453;
        double beta = 1.0 - (double)a / (double)N_COLS;
        sh_row[r] = (beta * (double)b + (1.0 - beta) * (double)c) * LN2;
    }
    __syncthreads();

    if (tid < 64) {
        double s = sh_row[tid];
#pragma unroll
        for (int o = 16; o > 0; o >>= 1)
            s += __shfl_down_sync(0xFFFFFFFFu, s, o);
        __shared__ double sh2[2];
        if ((tid & 31) == 0) sh2[tid >> 5] = s;
        __syncthreads();
        if (tid == 0) out[0] = (float)(-(sh2[0] + sh2[1]));
    }
}

extern "C" void kernel_launch(void* const* d_in, const int* in_sizes, int n_in,
                              void* d_out, int out_size) {
    const float* p = (const float*)d_in[0];  // input (probabilities)
    const float* t = (const float*)d_in[1];  // target
    float* out = (float*)d_out;

    dim3 grid(BLOCKS_PER_ROW, B_ROWS);
    bce_main_kernel<<<grid, THREADS>>>(p, t);

    // Programmatic dependent launch of the finalize kernel.
    cudaLaunchConfig_t cfg = {};
    cfg.gridDim = dim3(1, 1, 1);
    cfg.blockDim = dim3(512, 1, 1);
    cfg.dynamicSmemBytes = 0;
    cfg.stream = 0;
    cudaLaunchAttribute attrs[1];
    attrs[0].id = cudaLaunchAttributeProgrammaticStreamSerialization;
    attrs[0].val.programmaticStreamSerializationAllowed = 1;
    cfg.attrs = attrs;
    cfg.numAttrs = 1;
    cudaLaunchKernelEx(&cfg, finalize_kernel, out);
}